// round 15
// baseline (speedup 1.0000x reference)
#include <cuda_runtime.h>
#include <cuda_bf16.h>
#include <math.h>
#include <stdint.h>

// ---------------- problem constants ----------------
#define BATCH 128
#define SEQ   512
#define EMB   300
#define EMBP  304          // padded K (mult of 16)
#define HID   128
#define G4    512          // 4*HID
#define NTAG  12
#define SOS_T 3
#define EOS_T 4
#define NEGV  (-10000.0f)
#define MTOT  (BATCH*SEQ)  // 65536
#define NTOT  1024         // both directions' gates

// ---------------- device scratch (static; no allocations) ----------------
__device__ float g_emb[(size_t)MTOT * EMBP];                  // ~80 MB  padded embeddings
__device__ float g_wt [(size_t)EMBP * NTOT];                  // 1.2 MB  staged [K][N] weights
__device__ float g_bias[NTOT];
__device__ __nv_bfloat16 g_gx [(size_t)2 * MTOT * G4];        // ~134 MB input projections (+bias), bf16
__device__ float g_H  [(size_t)2 * 513 * BATCH * HID];        // ~67 MB  hidden states
__device__ float g_y  [(size_t)MTOT * NTAG];                  // 3 MB    emissions

// ---------------- helpers ----------------
__device__ __forceinline__ float tanh_ap(float x) {
    float y; asm("tanh.approx.f32 %0, %1;" : "=f"(y) : "f"(x)); return y;
}
__device__ __forceinline__ float sig_ap(float x) {
    return 0.5f * tanh_ap(0.5f * x) + 0.5f;
}
__device__ __forceinline__ uint32_t f2tf(float f) {
    uint32_t u; asm("cvt.rna.tf32.f32 %0, %1;" : "=r"(u) : "f"(f)); return u;
}
__device__ __forceinline__ void mma_tf32(float* c, const uint32_t* a, const uint32_t* b) {
    asm volatile(
        "mma.sync.aligned.m16n8k8.row.col.f32.tf32.tf32.f32 "
        "{%0,%1,%2,%3}, {%4,%5,%6,%7}, {%8,%9}, {%0,%1,%2,%3};"
        : "+f"(c[0]), "+f"(c[1]), "+f"(c[2]), "+f"(c[3])
        : "r"(a[0]), "r"(a[1]), "r"(a[2]), "r"(a[3]), "r"(b[0]), "r"(b[1]));
}
__device__ __forceinline__ void mma_bf16(float* c, const uint32_t* a, uint32_t b0, uint32_t b1) {
    asm volatile(
        "mma.sync.aligned.m16n8k16.row.col.f32.bf16.bf16.f32 "
        "{%0,%1,%2,%3}, {%4,%5,%6,%7}, {%8,%9}, {%0,%1,%2,%3};"
        : "+f"(c[0]), "+f"(c[1]), "+f"(c[2]), "+f"(c[3])
        : "r"(a[0]), "r"(a[1]), "r"(a[2]), "r"(a[3]), "r"(b0), "r"(b1));
}
__device__ __forceinline__ uint32_t pack_bf16(float lo, float hi) {
    __nv_bfloat162 p = __floats2bfloat162_rn(lo, hi);
    return *(uint32_t*)&p;
}

// ================= stage weights: g_wt[k][n], g_bias =================
__global__ void stage_w_kernel(const float* __restrict__ Wih_f,
                               const float* __restrict__ Wih_b,
                               const float* __restrict__ b_f,
                               const float* __restrict__ b_b) {
    int idx = blockIdx.x * blockDim.x + threadIdx.x;     // over EMBP*NTOT
    if (idx < EMBP * NTOT) {
        int k = idx / NTOT, n = idx % NTOT;
        float v = 0.0f;
        if (k < EMB) v = (n < G4) ? Wih_f[n * EMB + k] : Wih_b[(n - G4) * EMB + k];
        g_wt[idx] = v;
        if (k == 0) g_bias[n] = (n < G4) ? b_f[n] : b_b[n - G4];
    }
}

// ================= gather embeddings (padded) =================
__global__ void gather_kernel(const int* __restrict__ x,
                              const float* __restrict__ embed) {
    int m = blockIdx.x;                 // 0..MTOT-1
    int xi = x[m];
    const float* src = embed + (size_t)xi * EMB;
    float* dst = g_emb + (size_t)m * EMBP;
    for (int k = threadIdx.x; k < EMBP; k += blockDim.x)
        dst[k] = (k < EMB) ? src[k] : 0.0f;
}

// ================= input-projection GEMM (TF32 tensor cores, bf16 output) =====
#define AS_STRIDE 20
#define BS_STRIDE 136
__global__ __launch_bounds__(256) void gemm_kernel() {
    __shared__ __align__(16) uint32_t As[128 * AS_STRIDE];
    __shared__ __align__(16) uint32_t Bs[16 * BS_STRIDE];

    const int tid = threadIdx.x;
    const int m0 = blockIdx.y * 128, n0 = blockIdx.x * 128;

    const int warp = tid >> 5, lane = tid & 31;
    const int wm = (warp >> 2) * 64, wn = (warp & 3) * 32;
    const int r = lane >> 2, c = lane & 3;

    const int am = tid >> 1, akc = (tid & 1) * 8;
    const int bk = tid >> 5, bnc = (tid & 31) * 4;

    const float* Ap = g_emb + (size_t)(m0 + am) * EMBP + akc;
    const float* Bp = g_wt + (size_t)bk * NTOT + n0 + bnc;

    float acc[4][4][4];
#pragma unroll
    for (int i = 0; i < 4; ++i)
#pragma unroll
        for (int j = 0; j < 4; ++j)
#pragma unroll
            for (int q = 0; q < 4; ++q) acc[i][j][q] = 0.0f;

    float4 av0 = *(const float4*)(Ap);
    float4 av1 = *(const float4*)(Ap + 4);
    float4 bv0 = *(const float4*)(Bp);
    float4 bv1 = *(const float4*)(Bp + (size_t)8 * NTOT);

    for (int k0 = 0; k0 < EMBP; k0 += 16) {
        {
            uint4 ua0 = make_uint4(f2tf(av0.x), f2tf(av0.y), f2tf(av0.z), f2tf(av0.w));
            uint4 ua1 = make_uint4(f2tf(av1.x), f2tf(av1.y), f2tf(av1.z), f2tf(av1.w));
            *(uint4*)&As[am * AS_STRIDE + akc]     = ua0;
            *(uint4*)&As[am * AS_STRIDE + akc + 4] = ua1;
            uint4 ub0 = make_uint4(f2tf(bv0.x), f2tf(bv0.y), f2tf(bv0.z), f2tf(bv0.w));
            uint4 ub1 = make_uint4(f2tf(bv1.x), f2tf(bv1.y), f2tf(bv1.z), f2tf(bv1.w));
            *(uint4*)&Bs[bk * BS_STRIDE + bnc]       = ub0;
            *(uint4*)&Bs[(bk + 8) * BS_STRIDE + bnc] = ub1;
        }
        __syncthreads();
        if (k0 + 16 < EMBP) {
            av0 = *(const float4*)(Ap + k0 + 16);
            av1 = *(const float4*)(Ap + k0 + 20);
            bv0 = *(const float4*)(Bp + (size_t)(k0 + 16) * NTOT);
            bv1 = *(const float4*)(Bp + (size_t)(k0 + 24) * NTOT);
        }
#pragma unroll
        for (int kh = 0; kh < 16; kh += 8) {
            uint32_t af[4][4], bf[4][2];
#pragma unroll
            for (int i = 0; i < 4; ++i) {
                const uint32_t* ap = &As[(wm + i * 16 + r) * AS_STRIDE + kh + c];
                af[i][0] = ap[0];
                af[i][1] = ap[8 * AS_STRIDE];
                af[i][2] = ap[4];
                af[i][3] = ap[8 * AS_STRIDE + 4];
            }
#pragma unroll
            for (int j = 0; j < 4; ++j) {
                const uint32_t* bp = &Bs[(kh + c) * BS_STRIDE + wn + j * 8 + r];
                bf[j][0] = bp[0];
                bf[j][1] = bp[4 * BS_STRIDE];
            }
#pragma unroll
            for (int i = 0; i < 4; ++i)
#pragma unroll
                for (int j = 0; j < 4; ++j)
                    mma_tf32(acc[i][j], af[i], bf[j]);
        }
        __syncthreads();
    }

    const int dir = n0 >> 9;
    __nv_bfloat16* outb = g_gx + (size_t)dir * MTOT * G4;
#pragma unroll
    for (int j = 0; j < 4; ++j) {
        const int n = n0 + wn + j * 8 + c * 2;
        const int grow = n & 511;
        const float2 bias = *(const float2*)&g_bias[n];
#pragma unroll
        for (int i = 0; i < 4; ++i) {
            const int m = m0 + wm + i * 16 + r;
            __nv_bfloat162 p0 = __floats2bfloat162_rn(acc[i][j][0] + bias.x,
                                                      acc[i][j][1] + bias.y);
            __nv_bfloat162 p1 = __floats2bfloat162_rn(acc[i][j][2] + bias.x,
                                                      acc[i][j][3] + bias.y);
            *(__nv_bfloat162*)(outb + (size_t)m * G4 + grow)       = p0;
            *(__nv_bfloat162*)(outb + (size_t)(m + 8) * G4 + grow) = p1;
        }
    }
}

// ================= persistent LSTM recurrence (bf16 MMA, gate-grouped) ========
// 32 CTAs = 2 dirs x 16 batch-groups(8). 256 threads (8 warps).
// Warp w's 4 m-tiles = the FOUR GATES of units [w*16, w*16+16): tile g covers
// rows g*128 + w*16 + {gid, gid+8}. After the MMAs each thread holds i,f,g,o
// for its 4 (unit,batch) pairs IN REGISTERS — no gate exchange, no ex smem.
// h goes to a parity double-buffered hBs (write buf t+1, read buf t) ->
// ONE bar.sync per step. gx register-prefetched 1 step ahead (16 scalar LDG).
#define HBS 136   // hB row stride in bf16 ([batch][unit], conflict-free B-frags)
__global__ __launch_bounds__(256, 1)
void recur_kernel(const float* __restrict__ Whh_f,
                  const float* __restrict__ Whh_b) {
    __shared__ __align__(16) __nv_bfloat16 hBs[2][8 * HBS];   // [parity][batch][unit]

    const int cta = blockIdx.x;          // 32 CTAs
    const int dir = cta >> 4;
    const int grp = cta & 15;
    const int b0  = grp * 8;

    const int tid  = threadIdx.x;
    const int warp = tid >> 5, lane = tid & 31;
    const int gid  = lane >> 2, tid2 = lane & 3;
    const int u0   = warp * 16 + gid;    // this thread's units: u0, u0+8
    const int bA   = 2 * tid2, bB = bA + 1;

    const float* Whh = dir ? Whh_b : Whh_f;
    const __nv_bfloat16* gx = g_gx + (size_t)dir * MTOT * G4;
    float* Hbuf = g_H + (size_t)dir * 513 * BATCH * HID;

    // ---- hoist Whh into bf16 A-fragments, m-tile = gate ----
    uint32_t wfrag[4][8][4];
#pragma unroll
    for (int g = 0; g < 4; ++g) {
#pragma unroll
        for (int kt = 0; kt < 8; ++kt) {
            const int r0 = g * 128 + u0;
            const int k0 = kt * 16 + tid2 * 2;
            const float* w0 = Whh + (size_t)r0 * HID + k0;
            const float* w1 = Whh + (size_t)(r0 + 8) * HID + k0;
            wfrag[g][kt][0] = pack_bf16(w0[0], w0[1]);
            wfrag[g][kt][1] = pack_bf16(w1[0], w1[1]);
            wfrag[g][kt][2] = pack_bf16(w0[8], w0[9]);
            wfrag[g][kt][3] = pack_bf16(w1[8], w1[9]);
        }
    }

    // ---- zero h buffers, init c ----
    for (int i = tid; i < 8 * HBS; i += 256) {
        hBs[0][i] = __float2bfloat16(0.0f);
        hBs[1][i] = __float2bfloat16(0.0f);
    }
    float cst[4] = {0.0f, 0.0f, 0.0f, 0.0f};

    auto sidx = [&](int t) { return dir ? (SEQ - 1 - t) : t; };
    const ptrdiff_t sstep = dir ? -(ptrdiff_t)G4 : (ptrdiff_t)G4;

    // gx pointers per pair: p0=(u0,bA) p1=(u0,bB) p2=(u0+8,bA) p3=(u0+8,bB)
    const __nv_bfloat16* gp[4];
    gp[0] = gx + ((size_t)(b0 + bA) * SEQ + sidx(0)) * G4 + u0;
    gp[1] = gx + ((size_t)(b0 + bB) * SEQ + sidx(0)) * G4 + u0;
    gp[2] = gp[0] + 8;
    gp[3] = gp[1] + 8;

    // prefetch gx for step 0
    float gxv[4][4];                     // [pair][gate]
#pragma unroll
    for (int p = 0; p < 4; ++p)
#pragma unroll
        for (int g = 0; g < 4; ++g)
            gxv[p][g] = __bfloat162float(gp[p][g * 128]);
#pragma unroll
    for (int p = 0; p < 4; ++p) gp[p] += sstep;

    __syncthreads();

    for (int t = 0; t < SEQ; ++t) {
        const int s = sidx(t);
        const int wslot = dir ? s : (s + 1);
        const int buf = t & 1;

        // ---- early prefetch gx for step t+1 (latency hides under MMA+gates) --
        float gxn[4][4];
        if (t + 1 < SEQ) {
#pragma unroll
            for (int p = 0; p < 4; ++p)
#pragma unroll
                for (int g = 0; g < 4; ++g)
                    gxn[p][g] = __bfloat162float(gp[p][g * 128]);
#pragma unroll
            for (int p = 0; p < 4; ++p) gp[p] += sstep;
        }

        // ---- MMA: all four gates of my units, in registers ----
        float acc[4][4];
#pragma unroll
        for (int g = 0; g < 4; ++g)
#pragma unroll
            for (int q = 0; q < 4; ++q) acc[g][q] = 0.0f;

#pragma unroll
        for (int kt = 0; kt < 8; ++kt) {
            const __nv_bfloat16* hb = &hBs[buf][gid * HBS + kt * 16 + tid2 * 2];
            uint32_t br0 = *(const uint32_t*)hb;
            uint32_t br1 = *(const uint32_t*)(hb + 8);
#pragma unroll
            for (int g = 0; g < 4; ++g)
                mma_bf16(acc[g], wfrag[g][kt], br0, br1);
        }

        // ---- cell/h update, all in registers; publish h ----
        float* Hw = Hbuf + (size_t)wslot * BATCH * HID + (size_t)b0 * HID;
        __nv_bfloat16* hW = hBs[buf ^ 1];
        const int pu[4] = {u0, u0, u0 + 8, u0 + 8};
        const int pb[4] = {bA, bB, bA, bB};
#pragma unroll
        for (int p = 0; p < 4; ++p) {
            float iv = acc[0][p] + gxv[p][0];
            float fv = acc[1][p] + gxv[p][1];
            float gv = acc[2][p] + gxv[p][2];
            float ov = acc[3][p] + gxv[p][3];
            cst[p] = sig_ap(fv) * cst[p] + sig_ap(iv) * tanh_ap(gv);
            float h = sig_ap(ov) * tanh_ap(cst[p]);
            Hw[pb[p] * HID + pu[p]] = h;
            hW[pb[p] * HBS + pu[p]] = __float2bfloat16(h);
        }

        // carry prefetched gx
#pragma unroll
        for (int p = 0; p < 4; ++p)
#pragma unroll
            for (int g = 0; g < 4; ++g) gxv[p][g] = gxn[p][g];

        __syncthreads();
    }
}

// ================= output linear: y = [hf,hb] @ Wout^T + bout =================
__global__ __launch_bounds__(64) void outlin_kernel(const float* __restrict__ Wout,
                                                    const float* __restrict__ bout) {
    __shared__ float Ws[NTAG * 256];
    __shared__ float bs[NTAG];
    for (int i = threadIdx.x; i < NTAG * 256; i += 64) Ws[i] = Wout[i];
    if (threadIdx.x < NTAG) bs[threadIdx.x] = bout[threadIdx.x];
    __syncthreads();

    int m = blockIdx.x * 64 + threadIdx.x;    // 0..MTOT-1
    int b = m >> 9, s = m & 511;
    const float* hf = g_H + (size_t)(s + 1) * BATCH * HID + (size_t)b * HID;
    const float* hb = g_H + (size_t)513 * BATCH * HID + (size_t)s * BATCH * HID + (size_t)b * HID;

    float acc[NTAG];
#pragma unroll
    for (int tg = 0; tg < NTAG; ++tg) acc[tg] = bs[tg];

#pragma unroll 4
    for (int j = 0; j < 128; j += 4) {
        float4 hv = *(const float4*)(hf + j);
#pragma unroll
        for (int tg = 0; tg < NTAG; ++tg) {
            const float* wr = &Ws[tg * 256 + j];
            acc[tg] += hv.x * wr[0] + hv.y * wr[1] + hv.z * wr[2] + hv.w * wr[3];
        }
    }
#pragma unroll 4
    for (int j = 0; j < 128; j += 4) {
        float4 hv = *(const float4*)(hb + j);
#pragma unroll
        for (int tg = 0; tg < NTAG; ++tg) {
            const float* wr = &Ws[tg * 256 + 128 + j];
            acc[tg] += hv.x * wr[0] + hv.y * wr[1] + hv.z * wr[2] + hv.w * wr[3];
        }
    }
    float* yo = g_y + (size_t)m * NTAG;
#pragma unroll
    for (int tg = 0; tg < NTAG; ++tg) yo[tg] = acc[tg];
}

// ================= CRF: forward partition + gold score =================
__global__ void crf_kernel(const float* __restrict__ trans,
                           const int* __restrict__ y0,
                           float* __restrict__ out) {
    const int b = blockIdx.x;
    const int lane = threadIdx.x;     // 32 threads

    float tr[NTAG];
#pragma unroll
    for (int j = 0; j < NTAG; ++j)
        tr[j] = (lane < NTAG) ? trans[lane * NTAG + j] : NEGV;

    float sc[NTAG];
#pragma unroll
    for (int j = 0; j < NTAG; ++j) sc[j] = (j == SOS_T) ? 0.0f : NEGV;

    const float* ye = g_y + (size_t)b * SEQ * NTAG;

    for (int t = 0; t < SEQ; ++t) {
        float e = (lane < NTAG) ? ye[t * NTAG + lane] : 0.0f;
        float m = -1e30f;
        float v[NTAG];
#pragma unroll
        for (int j = 0; j < NTAG; ++j) { v[j] = sc[j] + tr[j]; m = fmaxf(m, v[j]); }
        float ssum = 0.0f;
#pragma unroll
        for (int j = 0; j < NTAG; ++j) ssum += __expf(v[j] - m);
        float nw = m + logf(ssum) + e;
#pragma unroll
        for (int j = 0; j < NTAG; ++j) sc[j] = __shfl_sync(0xFFFFFFFFu, nw, j);
    }

    float zv = (lane < NTAG) ? sc[lane] + trans[EOS_T * NTAG + lane] : -1e30f;
    float zm = zv;
#pragma unroll
    for (int o = 16; o > 0; o >>= 1) zm = fmaxf(zm, __shfl_xor_sync(0xFFFFFFFFu, zm, o));
    float ze = (lane < NTAG) ? __expf(zv - zm) : 0.0f;
#pragma unroll
    for (int o = 16; o > 0; o >>= 1) ze += __shfl_xor_sync(0xFFFFFFFFu, ze, o);
    float Z = zm + logf(ze);

    const int* yb = y0 + (size_t)b * SEQ;
    float g = 0.0f;
    for (int s = lane; s < SEQ; s += 32) {
        int yt = yb[s];
        int yp = (s == 0) ? SOS_T : yb[s - 1];
        g += ye[s * NTAG + yt] + trans[yt * NTAG + yp];
    }
#pragma unroll
    for (int o = 16; o > 0; o >>= 1) g += __shfl_xor_sync(0xFFFFFFFFu, g, o);

    if (lane == 0) {
        g += trans[EOS_T * NTAG + yb[SEQ - 1]];
        out[b] = Z - g;
    }
}

// ================= launch =================
extern "C" void kernel_launch(void* const* d_in, const int* in_sizes, int n_in,
                              void* d_out, int out_size) {
    const int*   x     = (const int*)d_in[0];
    const int*   y0    = (const int*)d_in[1];
    const float* embed = (const float*)d_in[2];
    const float* Wih_f = (const float*)d_in[3];
    const float* Whh_f = (const float*)d_in[4];
    const float* b_f   = (const float*)d_in[5];
    const float* Wih_b = (const float*)d_in[6];
    const float* Whh_b = (const float*)d_in[7];
    const float* b_b   = (const float*)d_in[8];
    const float* Wout  = (const float*)d_in[9];
    const float* bout  = (const float*)d_in[10];
    const float* trans = (const float*)d_in[11];
    float* out = (float*)d_out;

    stage_w_kernel<<<(EMBP * NTOT + 255) / 256, 256>>>(Wih_f, Wih_b, b_f, b_b);
    gather_kernel<<<MTOT, 128>>>(x, embed);
    gemm_kernel<<<dim3(8, 512), 256>>>();
    recur_kernel<<<32, 256>>>(Whh_f, Whh_b);
    outlin_kernel<<<MTOT / 64, 64>>>(Wout, bout);
    crf_kernel<<<BATCH, 32>>>(trans, y0, out);
}

// round 16
// speedup vs baseline: 1.4338x; 1.4338x over previous
#include <cuda_runtime.h>
#include <cuda_bf16.h>
#include <math.h>
#include <stdint.h>

// ---------------- problem constants ----------------
#define BATCH 128
#define SEQ   512
#define EMB   300
#define EMBP  304          // padded K (mult of 16)
#define HID   128
#define G4    512          // 4*HID
#define NTAG  12
#define SOS_T 3
#define EOS_T 4
#define NEGV  (-10000.0f)
#define MTOT  (BATCH*SEQ)  // 65536
#define NTOT  1024         // both directions' gates

// ---------------- device scratch (static; no allocations) ----------------
__device__ float g_emb[(size_t)MTOT * EMBP];                  // ~80 MB  padded embeddings
__device__ float g_wt [(size_t)EMBP * NTOT];                  // 1.2 MB  staged [K][N] weights
__device__ float g_bias[NTOT];
__device__ __nv_bfloat16 g_gx [(size_t)2 * MTOT * G4];        // ~134 MB input projections (+bias), bf16
__device__ float g_H  [(size_t)2 * 513 * BATCH * HID];        // ~67 MB  hidden states
__device__ float g_y  [(size_t)MTOT * NTAG];                  // 3 MB    emissions

// ---------------- helpers ----------------
__device__ __forceinline__ float tanh_ap(float x) {
    float y; asm("tanh.approx.f32 %0, %1;" : "=f"(y) : "f"(x)); return y;
}
__device__ __forceinline__ float sig_ap(float x) {
    return 0.5f * tanh_ap(0.5f * x) + 0.5f;
}
__device__ __forceinline__ uint32_t f2tf(float f) {
    uint32_t u; asm("cvt.rna.tf32.f32 %0, %1;" : "=r"(u) : "f"(f)); return u;
}
__device__ __forceinline__ void mma_tf32(float* c, const uint32_t* a, const uint32_t* b) {
    asm volatile(
        "mma.sync.aligned.m16n8k8.row.col.f32.tf32.tf32.f32 "
        "{%0,%1,%2,%3}, {%4,%5,%6,%7}, {%8,%9}, {%0,%1,%2,%3};"
        : "+f"(c[0]), "+f"(c[1]), "+f"(c[2]), "+f"(c[3])
        : "r"(a[0]), "r"(a[1]), "r"(a[2]), "r"(a[3]), "r"(b[0]), "r"(b[1]));
}
__device__ __forceinline__ void mma_bf16(float* c, const uint32_t* a, uint32_t b0, uint32_t b1) {
    asm volatile(
        "mma.sync.aligned.m16n8k16.row.col.f32.bf16.bf16.f32 "
        "{%0,%1,%2,%3}, {%4,%5,%6,%7}, {%8,%9}, {%0,%1,%2,%3};"
        : "+f"(c[0]), "+f"(c[1]), "+f"(c[2]), "+f"(c[3])
        : "r"(a[0]), "r"(a[1]), "r"(a[2]), "r"(a[3]), "r"(b0), "r"(b1));
}
__device__ __forceinline__ uint32_t pack_bf16(float lo, float hi) {
    __nv_bfloat162 p = __floats2bfloat162_rn(lo, hi);
    return *(uint32_t*)&p;
}

// ================= stage weights: g_wt[k][n], g_bias =================
__global__ void stage_w_kernel(const float* __restrict__ Wih_f,
                               const float* __restrict__ Wih_b,
                               const float* __restrict__ b_f,
                               const float* __restrict__ b_b) {
    int idx = blockIdx.x * blockDim.x + threadIdx.x;     // over EMBP*NTOT
    if (idx < EMBP * NTOT) {
        int k = idx / NTOT, n = idx % NTOT;
        float v = 0.0f;
        if (k < EMB) v = (n < G4) ? Wih_f[n * EMB + k] : Wih_b[(n - G4) * EMB + k];
        g_wt[idx] = v;
        if (k == 0) g_bias[n] = (n < G4) ? b_f[n] : b_b[n - G4];
    }
}

// ================= gather embeddings (padded) =================
__global__ void gather_kernel(const int* __restrict__ x,
                              const float* __restrict__ embed) {
    int m = blockIdx.x;                 // 0..MTOT-1
    int xi = x[m];
    const float* src = embed + (size_t)xi * EMB;
    float* dst = g_emb + (size_t)m * EMBP;
    for (int k = threadIdx.x; k < EMBP; k += blockDim.x)
        dst[k] = (k < EMB) ? src[k] : 0.0f;
}

// ================= input-projection GEMM (TF32 tensor cores, bf16 output) =====
#define AS_STRIDE 20
#define BS_STRIDE 136
__global__ __launch_bounds__(256) void gemm_kernel() {
    __shared__ __align__(16) uint32_t As[128 * AS_STRIDE];
    __shared__ __align__(16) uint32_t Bs[16 * BS_STRIDE];

    const int tid = threadIdx.x;
    const int m0 = blockIdx.y * 128, n0 = blockIdx.x * 128;

    const int warp = tid >> 5, lane = tid & 31;
    const int wm = (warp >> 2) * 64, wn = (warp & 3) * 32;
    const int r = lane >> 2, c = lane & 3;

    const int am = tid >> 1, akc = (tid & 1) * 8;
    const int bk = tid >> 5, bnc = (tid & 31) * 4;

    const float* Ap = g_emb + (size_t)(m0 + am) * EMBP + akc;
    const float* Bp = g_wt + (size_t)bk * NTOT + n0 + bnc;

    float acc[4][4][4];
#pragma unroll
    for (int i = 0; i < 4; ++i)
#pragma unroll
        for (int j = 0; j < 4; ++j)
#pragma unroll
            for (int q = 0; q < 4; ++q) acc[i][j][q] = 0.0f;

    float4 av0 = *(const float4*)(Ap);
    float4 av1 = *(const float4*)(Ap + 4);
    float4 bv0 = *(const float4*)(Bp);
    float4 bv1 = *(const float4*)(Bp + (size_t)8 * NTOT);

    for (int k0 = 0; k0 < EMBP; k0 += 16) {
        {
            uint4 ua0 = make_uint4(f2tf(av0.x), f2tf(av0.y), f2tf(av0.z), f2tf(av0.w));
            uint4 ua1 = make_uint4(f2tf(av1.x), f2tf(av1.y), f2tf(av1.z), f2tf(av1.w));
            *(uint4*)&As[am * AS_STRIDE + akc]     = ua0;
            *(uint4*)&As[am * AS_STRIDE + akc + 4] = ua1;
            uint4 ub0 = make_uint4(f2tf(bv0.x), f2tf(bv0.y), f2tf(bv0.z), f2tf(bv0.w));
            uint4 ub1 = make_uint4(f2tf(bv1.x), f2tf(bv1.y), f2tf(bv1.z), f2tf(bv1.w));
            *(uint4*)&Bs[bk * BS_STRIDE + bnc]       = ub0;
            *(uint4*)&Bs[(bk + 8) * BS_STRIDE + bnc] = ub1;
        }
        __syncthreads();
        if (k0 + 16 < EMBP) {
            av0 = *(const float4*)(Ap + k0 + 16);
            av1 = *(const float4*)(Ap + k0 + 20);
            bv0 = *(const float4*)(Bp + (size_t)(k0 + 16) * NTOT);
            bv1 = *(const float4*)(Bp + (size_t)(k0 + 24) * NTOT);
        }
#pragma unroll
        for (int kh = 0; kh < 16; kh += 8) {
            uint32_t af[4][4], bf[4][2];
#pragma unroll
            for (int i = 0; i < 4; ++i) {
                const uint32_t* ap = &As[(wm + i * 16 + r) * AS_STRIDE + kh + c];
                af[i][0] = ap[0];
                af[i][1] = ap[8 * AS_STRIDE];
                af[i][2] = ap[4];
                af[i][3] = ap[8 * AS_STRIDE + 4];
            }
#pragma unroll
            for (int j = 0; j < 4; ++j) {
                const uint32_t* bp = &Bs[(kh + c) * BS_STRIDE + wn + j * 8 + r];
                bf[j][0] = bp[0];
                bf[j][1] = bp[4 * BS_STRIDE];
            }
#pragma unroll
            for (int i = 0; i < 4; ++i)
#pragma unroll
                for (int j = 0; j < 4; ++j)
                    mma_tf32(acc[i][j], af[i], bf[j]);
        }
        __syncthreads();
    }

    const int dir = n0 >> 9;
    __nv_bfloat16* outb = g_gx + (size_t)dir * MTOT * G4;
#pragma unroll
    for (int j = 0; j < 4; ++j) {
        const int n = n0 + wn + j * 8 + c * 2;
        const int grow = n & 511;
        const float2 bias = *(const float2*)&g_bias[n];
#pragma unroll
        for (int i = 0; i < 4; ++i) {
            const int m = m0 + wm + i * 16 + r;
            __nv_bfloat162 p0 = __floats2bfloat162_rn(acc[i][j][0] + bias.x,
                                                      acc[i][j][1] + bias.y);
            __nv_bfloat162 p1 = __floats2bfloat162_rn(acc[i][j][2] + bias.x,
                                                      acc[i][j][3] + bias.y);
            *(__nv_bfloat162*)(outb + (size_t)m * G4 + grow)       = p0;
            *(__nv_bfloat162*)(outb + (size_t)(m + 8) * G4 + grow) = p1;
        }
    }
}

// ================= persistent LSTM recurrence (bf16 MMA, 16 warps) ============
// 32 CTAs = 2 dirs x 16 batch-groups(8). 512 threads (16 warps).
// Warp w owns units [w*8, w*8+8). Two m-tiles, each packing TWO gates:
//   tile0 rows: {0*128+u (i), 1*128+u (f)}, tile1 rows: {2*128+u (g), 3*128+u (o)}
//   (tile row gid -> gate-even, row gid+8 -> gate-odd; verified by R15 pass).
// wfrag = 64 regs/thread -> no spills; 4 warps/SMSP hides MMA/MUFU latency.
// gx: ONE coalesced uint4 LDG per thread per step, double-buffered in smem.
// hBs parity double buffer; ONE bar.sync per step.
#define HBS 136   // hB row stride in bf16 ([batch][unit], conflict-free B-frags)
#define GXS 520   // gxs row stride in bf16 (bank-conflict-free gate reads)
__global__ __launch_bounds__(512, 1)
void recur_kernel(const float* __restrict__ Whh_f,
                  const float* __restrict__ Whh_b) {
    __shared__ __align__(16) __nv_bfloat16 hBs[2][8 * HBS];   // [parity][batch][unit]
    __shared__ __align__(16) __nv_bfloat16 gxs[2][8 * GXS];   // [parity][batch][gate-row]

    const int cta = blockIdx.x;          // 32 CTAs
    const int dir = cta >> 4;
    const int grp = cta & 15;
    const int b0  = grp * 8;

    const int tid  = threadIdx.x;
    const int warp = tid >> 5, lane = tid & 31;
    const int gid  = lane >> 2, tid2 = lane & 3;
    const int u    = warp * 8 + gid;     // this thread's unit
    const int bA   = 2 * tid2, bB = bA + 1;

    const float* Whh = dir ? Whh_b : Whh_f;
    const __nv_bfloat16* gx = g_gx + (size_t)dir * MTOT * G4;
    float* Hbuf = g_H + (size_t)dir * 513 * BATCH * HID;

    // ---- hoist Whh into bf16 A-fragments: tile T packs gates (2T, 2T+1) ----
    uint32_t wfrag[2][8][4];
#pragma unroll
    for (int T = 0; T < 2; ++T) {
#pragma unroll
        for (int kt = 0; kt < 8; ++kt) {
            const int k0 = kt * 16 + tid2 * 2;
            const float* wA = Whh + (size_t)((2 * T)     * 128 + u) * HID + k0;
            const float* wB = Whh + (size_t)((2 * T + 1) * 128 + u) * HID + k0;
            wfrag[T][kt][0] = pack_bf16(wA[0], wA[1]);
            wfrag[T][kt][1] = pack_bf16(wB[0], wB[1]);
            wfrag[T][kt][2] = pack_bf16(wA[8], wA[9]);
            wfrag[T][kt][3] = pack_bf16(wB[8], wB[9]);
        }
    }

    // ---- zero h buffers, init c ----
    for (int i = tid; i < 8 * HBS; i += 512) {
        hBs[0][i] = __float2bfloat16(0.0f);
        hBs[1][i] = __float2bfloat16(0.0f);
    }
    float cst[2] = {0.0f, 0.0f};

    auto sidx = [&](int t) { return dir ? (SEQ - 1 - t) : t; };

    // gx loader: thread covers row grow, 8 bf16 at gcol (coalesced uint4)
    const int grow = tid >> 6;
    const int gcol = (tid & 63) * 8;

    uint4 pv;
    {   // step 0 -> gxs[0]; step 1 -> regs
        const __nv_bfloat16* p0 = gx + ((size_t)(b0 + grow) * SEQ + sidx(0)) * G4 + gcol;
        uint4 v0 = *(const uint4*)p0;
        *(uint4*)&gxs[0][grow * GXS + gcol] = v0;
        const __nv_bfloat16* p1 = gx + ((size_t)(b0 + grow) * SEQ + sidx(1)) * G4 + gcol;
        pv = *(const uint4*)p1;
    }
    __syncthreads();

    for (int t = 0; t < SEQ; ++t) {
        const int s = sidx(t);
        const int wslot = dir ? s : (s + 1);
        const int buf = t & 1;

        // ---- MMA: tile0 = (i,f), tile1 = (g,o) for unit u, batches bA,bB ----
        float acc0[4] = {0.0f, 0.0f, 0.0f, 0.0f};
        float acc1[4] = {0.0f, 0.0f, 0.0f, 0.0f};
#pragma unroll
        for (int kt = 0; kt < 8; ++kt) {
            const __nv_bfloat16* hb = &hBs[buf][gid * HBS + kt * 16 + tid2 * 2];
            uint32_t br0 = *(const uint32_t*)hb;
            uint32_t br1 = *(const uint32_t*)(hb + 8);
            mma_bf16(acc0, wfrag[0][kt], br0, br1);
            mma_bf16(acc1, wfrag[1][kt], br0, br1);
        }

        // ---- gx pipeline: store regs (t+1) to gxs[buf^1]; load t+2 ----
        if (t + 1 < SEQ)
            *(uint4*)&gxs[buf ^ 1][grow * GXS + gcol] = pv;
        if (t + 2 < SEQ) {
            const __nv_bfloat16* p = gx + ((size_t)(b0 + grow) * SEQ + sidx(t + 2)) * G4 + gcol;
            pv = *(const uint4*)p;
        }

        // ---- gate math: pairs (u,bA), (u,bB); acc cols: c0=bA, c1=bB ----
        float* Hw = Hbuf + (size_t)wslot * BATCH * HID + (size_t)b0 * HID;
        __nv_bfloat16* hW = hBs[buf ^ 1];
        const __nv_bfloat16* gb = gxs[buf];
#pragma unroll
        for (int p = 0; p < 2; ++p) {
            const int b = p ? bB : bA;
            const __nv_bfloat16* gr = gb + b * GXS + u;
            float iv = acc0[p]     + __bfloat162float(gr[0]);
            float fv = acc0[2 + p] + __bfloat162float(gr[128]);
            float gv = acc1[p]     + __bfloat162float(gr[256]);
            float ov = acc1[2 + p] + __bfloat162float(gr[384]);
            cst[p] = sig_ap(fv) * cst[p] + sig_ap(iv) * tanh_ap(gv);
            float h = sig_ap(ov) * tanh_ap(cst[p]);
            Hw[b * HID + u] = h;
            hW[b * HBS + u] = __float2bfloat16(h);
        }

        __syncthreads();
    }
}

// ================= output linear: y = [hf,hb] @ Wout^T + bout =================
__global__ __launch_bounds__(64) void outlin_kernel(const float* __restrict__ Wout,
                                                    const float* __restrict__ bout) {
    __shared__ float Ws[NTAG * 256];
    __shared__ float bs[NTAG];
    for (int i = threadIdx.x; i < NTAG * 256; i += 64) Ws[i] = Wout[i];
    if (threadIdx.x < NTAG) bs[threadIdx.x] = bout[threadIdx.x];
    __syncthreads();

    int m = blockIdx.x * 64 + threadIdx.x;    // 0..MTOT-1
    int b = m >> 9, s = m & 511;
    const float* hf = g_H + (size_t)(s + 1) * BATCH * HID + (size_t)b * HID;
    const float* hb = g_H + (size_t)513 * BATCH * HID + (size_t)s * BATCH * HID + (size_t)b * HID;

    float acc[NTAG];
#pragma unroll
    for (int tg = 0; tg < NTAG; ++tg) acc[tg] = bs[tg];

#pragma unroll 4
    for (int j = 0; j < 128; j += 4) {
        float4 hv = *(const float4*)(hf + j);
#pragma unroll
        for (int tg = 0; tg < NTAG; ++tg) {
            const float* wr = &Ws[tg * 256 + j];
            acc[tg] += hv.x * wr[0] + hv.y * wr[1] + hv.z * wr[2] + hv.w * wr[3];
        }
    }
#pragma unroll 4
    for (int j = 0; j < 128; j += 4) {
        float4 hv = *(const float4*)(hb + j);
#pragma unroll
        for (int tg = 0; tg < NTAG; ++tg) {
            const float* wr = &Ws[tg * 256 + 128 + j];
            acc[tg] += hv.x * wr[0] + hv.y * wr[1] + hv.z * wr[2] + hv.w * wr[3];
        }
    }
    float* yo = g_y + (size_t)m * NTAG;
#pragma unroll
    for (int tg = 0; tg < NTAG; ++tg) yo[tg] = acc[tg];
}

// ================= CRF: forward partition + gold score =================
__global__ void crf_kernel(const float* __restrict__ trans,
                           const int* __restrict__ y0,
                           float* __restrict__ out) {
    const int b = blockIdx.x;
    const int lane = threadIdx.x;     // 32 threads

    float tr[NTAG];
#pragma unroll
    for (int j = 0; j < NTAG; ++j)
        tr[j] = (lane < NTAG) ? trans[lane * NTAG + j] : NEGV;

    float sc[NTAG];
#pragma unroll
    for (int j = 0; j < NTAG; ++j) sc[j] = (j == SOS_T) ? 0.0f : NEGV;

    const float* ye = g_y + (size_t)b * SEQ * NTAG;

    for (int t = 0; t < SEQ; ++t) {
        float e = (lane < NTAG) ? ye[t * NTAG + lane] : 0.0f;
        float m = -1e30f;
        float v[NTAG];
#pragma unroll
        for (int j = 0; j < NTAG; ++j) { v[j] = sc[j] + tr[j]; m = fmaxf(m, v[j]); }
        float ssum = 0.0f;
#pragma unroll
        for (int j = 0; j < NTAG; ++j) ssum += __expf(v[j] - m);
        float nw = m + logf(ssum) + e;
#pragma unroll
        for (int j = 0; j < NTAG; ++j) sc[j] = __shfl_sync(0xFFFFFFFFu, nw, j);
    }

    float zv = (lane < NTAG) ? sc[lane] + trans[EOS_T * NTAG + lane] : -1e30f;
    float zm = zv;
#pragma unroll
    for (int o = 16; o > 0; o >>= 1) zm = fmaxf(zm, __shfl_xor_sync(0xFFFFFFFFu, zm, o));
    float ze = (lane < NTAG) ? __expf(zv - zm) : 0.0f;
#pragma unroll
    for (int o = 16; o > 0; o >>= 1) ze += __shfl_xor_sync(0xFFFFFFFFu, ze, o);
    float Z = zm + logf(ze);

    const int* yb = y0 + (size_t)b * SEQ;
    float g = 0.0f;
    for (int s = lane; s < SEQ; s += 32) {
        int yt = yb[s];
        int yp = (s == 0) ? SOS_T : yb[s - 1];
        g += ye[s * NTAG + yt] + trans[yt * NTAG + yp];
    }
#pragma unroll
    for (int o = 16; o > 0; o >>= 1) g += __shfl_xor_sync(0xFFFFFFFFu, g, o);

    if (lane == 0) {
        g += trans[EOS_T * NTAG + yb[SEQ - 1]];
        out[b] = Z - g;
    }
}

// ================= launch =================
extern "C" void kernel_launch(void* const* d_in, const int* in_sizes, int n_in,
                              void* d_out, int out_size) {
    const int*   x     = (const int*)d_in[0];
    const int*   y0    = (const int*)d_in[1];
    const float* embed = (const float*)d_in[2];
    const float* Wih_f = (const float*)d_in[3];
    const float* Whh_f = (const float*)d_in[4];
    const float* b_f   = (const float*)d_in[5];
    const float* Wih_b = (const float*)d_in[6];
    const float* Whh_b = (const float*)d_in[7];
    const float* b_b   = (const float*)d_in[8];
    const float* Wout  = (const float*)d_in[9];
    const float* bout  = (const float*)d_in[10];
    const float* trans = (const float*)d_in[11];
    float* out = (float*)d_out;

    stage_w_kernel<<<(EMBP * NTOT + 255) / 256, 256>>>(Wih_f, Wih_b, b_f, b_b);
    gather_kernel<<<MTOT, 128>>>(x, embed);
    gemm_kernel<<<dim3(8, 512), 256>>>();
    recur_kernel<<<32, 512>>>(Whh_f, Whh_b);
    outlin_kernel<<<MTOT / 64, 64>>>(Wout, bout);
    crf_kernel<<<BATCH, 32>>>(trans, y0, out);
}